// round 17
// baseline (speedup 1.0000x reference)
#include <cuda_runtime.h>
#include <math.h>
#include <stdint.h>

#define B_    1024
#define C_    1024
#define E_    128
#define SPLIT 4
#define RPB   (C_ / SPLIT)    // 256 rows per fused block
#define TROWS 64              // compacted rows per pipeline stage (32KB)
#define EB    8               // batches per epilogue block
#define PB    4               // batches per prep block

// ---------------- device scratch (allocation-free rule) ----------------
__device__ float g_u [B_ * 8 * E_];
__device__ float g_qb[B_ * 8];
__device__ float g_pl[B_ * SPLIT * 8];
__device__ float g_ps[(size_t)B_ * SPLIT * 8 * E_];
__device__ float g_w [B_ * E_];
__device__ float g_kb[B_];
__device__ int   g_cidx[B_ * SPLIT * RPB];
__device__ int   g_cnt [B_ * SPLIT];
__device__ float g_VwT [E_ * E_];
__device__ float g_WowT[E_ * E_];
__device__ float g_QfwT[E_ * E_];
__device__ float g_QwT [384 * E_];

// ---------------- f32x2 helpers ----------------
__device__ __forceinline__ unsigned long long pk2(float x, float y) {
    unsigned long long r;
    asm("mov.b64 %0, {%1, %2};" : "=l"(r) : "f"(x), "f"(y));
    return r;
}
__device__ __forceinline__ float2 upk2(unsigned long long v) {
    float2 r;
    asm("mov.b64 {%0, %1}, %2;" : "=f"(r.x), "=f"(r.y) : "l"(v));
    return r;
}
#define MUL2(d, a, b) asm("mul.rn.f32x2 %0, %1, %2;" : "=l"(d) : "l"(a), "l"(b))
#define FMA2(d, a, b) asm("fma.rn.f32x2 %0, %1, %2, %0;" : "+l"(d) : "l"(a), "l"(b))

__device__ __forceinline__ void cp16(unsigned int dst, const void* src) {
    asm volatile("cp.async.cg.shared.global [%0], [%1], 16;" :: "r"(dst), "l"(src));
}

// ---------------------------------------------------------------------------
// K-setup: compact (all 4096 blocks) + weight transposes (first 384 blocks).
// ---------------------------------------------------------------------------
__global__ void __launch_bounds__(256) k_setup(
    const int* __restrict__ mask,
    const float* __restrict__ Vw, const float* __restrict__ Wow,
    const float* __restrict__ Qfw, const float* __restrict__ Qw)
{
    const int bp = blockIdx.y * SPLIT + blockIdx.x;
    const int tid = threadIdx.x, warp = tid >> 5, lane = tid & 31;

    __shared__ int wcnt[8], woff[8];

    int m = mask[blockIdx.y * C_ + blockIdx.x * RPB + tid];
    unsigned bal = __ballot_sync(0xffffffffu, m == 0);
    int pin = __popc(bal & ((1u << lane) - 1));
    if (lane == 0) wcnt[warp] = __popc(bal);
    __syncthreads();
    if (tid < 8) {
        int o = 0;
        for (int w = 0; w < tid; w++) o += wcnt[w];
        woff[tid] = o;
    }
    __syncthreads();
    if (m == 0) g_cidx[bp * RPB + woff[warp] + pin] = tid;
    if (tid == 255) g_cnt[bp] = woff[7] + wcnt[7];

    if (bp < 192) {
        int sel = bp >> 6;
        int i = (bp & 63) * 256 + tid;
        const float* src = sel == 0 ? Vw : (sel == 1 ? Wow : Qfw);
        float*       dst = sel == 0 ? g_VwT : (sel == 1 ? g_WowT : g_QfwT);
        dst[i] = src[(i & 127) * E_ + (i >> 7)];
    } else if (bp < 384) {
        int i = (bp - 192) * 256 + tid;
        g_QwT[i] = Qw[(i & 127) * 384 + (i >> 7)];
    }
}

// ---------------------------------------------------------------------------
// K0: 4 batches per block — weight rows load-once-use-4.
// ---------------------------------------------------------------------------
__global__ void __launch_bounds__(128) k_prep(
    const float* __restrict__ hN, const float* __restrict__ hpr,
    const float* __restrict__ h0,
    const float* __restrict__ Qb,
    const float* __restrict__ Vw, const float* __restrict__ Vb)
{
    const int b0 = blockIdx.x * PB, tid = threadIdx.x;
    __shared__ float hc_s[PB][384];
    __shared__ float q_s[PB][128];

    #pragma unroll
    for (int i = 0; i < PB; i++) {
        hc_s[i][tid]       = hN [(b0 + i) * E_ + tid];
        hc_s[i][128 + tid] = hpr[(b0 + i) * E_ + tid];
        hc_s[i][256 + tid] = h0 [(b0 + i) * E_ + tid];
    }
    __syncthreads();

    {
        float qb0 = Qb[tid];
        float a[PB];
        #pragma unroll
        for (int i = 0; i < PB; i++) a[i] = qb0;
        #pragma unroll 4
        for (int k = 0; k < 384; k++) {
            float w = g_QwT[k * 128 + tid];
            #pragma unroll
            for (int i = 0; i < PB; i++) a[i] += w * hc_s[i][k];
        }
        #pragma unroll
        for (int i = 0; i < PB; i++) q_s[i][tid] = a[i];
    }
    __syncthreads();

    #pragma unroll 1
    for (int hh = 0; hh < 8; hh++) {
        float a[PB];
        #pragma unroll
        for (int i = 0; i < PB; i++) a[i] = 0.0f;
        #pragma unroll
        for (int j = 0; j < 16; j++) {
            float w = Vw[(size_t)(hh * 16 + j) * E_ + tid];
            #pragma unroll
            for (int i = 0; i < PB; i++) a[i] += q_s[i][hh * 16 + j] * w;
        }
        #pragma unroll
        for (int i = 0; i < PB; i++)
            g_u[((size_t)(b0 + i) * 8 + hh) * E_ + tid] = 0.25f * a[i];
    }
    if (tid < 32) {
        int i = tid >> 3, hh = tid & 7;
        float a = 0.0f;
        #pragma unroll
        for (int j = 0; j < 16; j++)
            a += q_s[i][hh * 16 + j] * Vb[hh * 16 + j];
        g_qb[(b0 + i) * 8 + hh] = 0.25f * a;
    }
}

// ---------------------------------------------------------------------------
// K1: compacted cp.async pipeline; 4-row ILP groups; ulonglong2 tile loads.
// ---------------------------------------------------------------------------
__global__ void __launch_bounds__(256, 2) k_fused(const float* __restrict__ h)
{
    const int b = blockIdx.y, part = blockIdx.x;
    const int bp = b * SPLIT + part;
    const int tid = threadIdx.x, warp = tid >> 5, lane = tid & 31;
    const int hg = warp >> 2;
    const int ws = warp & 3;

    extern __shared__ float hbuf[];            // 2 stages x 8192 floats (64KB)
    __shared__ int   cidx_s[RPB];
    __shared__ float p_s[8][4][4];
    __shared__ float sl[8][4];

    const float* hb = h + (size_t)b * C_ * E_ + (size_t)part * RPB * E_;

    const int nU = g_cnt[bp];
    const int ns = (nU + TROWS - 1) / TROWS;
    cidx_s[tid] = g_cidx[bp * RPB + tid];
    __syncthreads();

    auto load_stage = [&](int t) {
        float* dst = hbuf + (t & 1) * 8192;
        #pragma unroll
        for (int k = 0; k < 8; k++) {
            int idx = k * 256 + tid;
            int i = t * TROWS + (idx >> 5);
            int j = idx & 31;
            if (i < nU) {
                unsigned int d = (unsigned int)__cvta_generic_to_shared(
                    dst + (idx >> 5) * 128 + j * 4);
                cp16(d, hb + (size_t)cidx_s[i] * E_ + j * 4);
            }
        }
    };

    load_stage(0);
    asm volatile("cp.async.commit_group;");
    load_stage(1);
    asm volatile("cp.async.commit_group;");

    unsigned long long u01[4], u23[4];
    #pragma unroll
    for (int hh = 0; hh < 4; hh++) {
        float4 uu = *(const float4*)&g_u[((size_t)b * 8 + hg * 4 + hh) * E_ + lane * 4];
        u01[hh] = pk2(uu.x, uu.y);
        u23[hh] = pk2(uu.z, uu.w);
    }
    const float qbr = g_qb[b * 8 + hg * 4 + (lane >> 3)];

    unsigned long long s2[8];
    #pragma unroll
    for (int i = 0; i < 8; i++) s2[i] = pk2(0.f, 0.f);
    float l_acc = 0.0f;

    const bool hi4 = (lane & 16) != 0;
    const bool hi3 = (lane & 8)  != 0;

    #pragma unroll 1
    for (int t = 0; t < ns; t++) {
        if (t == ns - 1) asm volatile("cp.async.wait_group 0;");
        else             asm volatile("cp.async.wait_group 1;");
        __syncthreads();

        const float* hs = hbuf + (t & 1) * 8192;
        int cnt_s = nU - t * TROWS;
        if (cnt_s > TROWS) cnt_s = TROWS;

        #pragma unroll 1
        for (int g = 0; ws + 16 * g < cnt_s; g++) {
            ulonglong2 c[4]; float v[4];
            #pragma unroll
            for (int j = 0; j < 4; j++) {
                int r = ws + 16 * g + 4 * j;
                bool ok = r < cnt_s;
                v[j] = ok ? 1.0f : 0.0f;
                int rr = ok ? r : ws + 16 * g;
                c[j] = *(const ulonglong2*)&hs[rr * 128 + lane * 4];
            }

            float d[4][4];
            #pragma unroll
            for (int j = 0; j < 4; j++)
                #pragma unroll
                for (int hh = 0; hh < 4; hh++) {
                    unsigned long long tt;
                    MUL2(tt, c[j].x, u01[hh]);
                    FMA2(tt, c[j].y, u23[hh]);
                    float2 t2 = upk2(tt);
                    d[j][hh] = t2.x + t2.y;
                }

            #pragma unroll
            for (int j = 0; j < 4; j++)
                #pragma unroll
                for (int q = 0; q < 2; q++) {
                    float send = hi4 ? d[j][q] : d[j][q + 2];
                    float keep = hi4 ? d[j][q + 2] : d[j][q];
                    d[j][q] = keep + __shfl_xor_sync(0xffffffffu, send, 16);
                }
            float dd[4];
            #pragma unroll
            for (int j = 0; j < 4; j++) {
                float send = hi3 ? d[j][0] : d[j][1];
                float keep = hi3 ? d[j][1] : d[j][0];
                dd[j] = keep + __shfl_xor_sync(0xffffffffu, send, 8);
            }
            #pragma unroll
            for (int j = 0; j < 4; j++)
                dd[j] += __shfl_xor_sync(0xffffffffu, dd[j], 4);
            #pragma unroll
            for (int j = 0; j < 4; j++)
                dd[j] += __shfl_xor_sync(0xffffffffu, dd[j], 2);
            #pragma unroll
            for (int j = 0; j < 4; j++)
                dd[j] += __shfl_xor_sync(0xffffffffu, dd[j], 1);

            float p[4];
            #pragma unroll
            for (int j = 0; j < 4; j++) {
                p[j] = __expf(dd[j] + qbr) * v[j];
                l_acc += p[j];
            }

            __syncwarp();
            if ((lane & 7) == 0) {
                const int k = lane >> 3;
                #pragma unroll
                for (int j = 0; j < 4; j++) p_s[warp][j][k] = p[j];
            }
            __syncwarp();

            #pragma unroll
            for (int j = 0; j < 4; j++) {
                float4 pq = *(const float4*)&p_s[warp][j][0];
                unsigned long long pd;
                pd = pk2(pq.x, pq.x); FMA2(s2[0], c[j].x, pd); FMA2(s2[1], c[j].y, pd);
                pd = pk2(pq.y, pq.y); FMA2(s2[2], c[j].x, pd); FMA2(s2[3], c[j].y, pd);
                pd = pk2(pq.z, pq.z); FMA2(s2[4], c[j].x, pd); FMA2(s2[5], c[j].y, pd);
                pd = pk2(pq.w, pq.w); FMA2(s2[6], c[j].x, pd); FMA2(s2[7], c[j].y, pd);
            }
        }

        __syncthreads();
        if (t + 2 < ns) {
            load_stage(t + 2);
            asm volatile("cp.async.commit_group;");
        }
    }

    float* sm = hbuf;
    #pragma unroll
    for (int hh = 0; hh < 4; hh++) {
        float2 e01 = upk2(s2[2 * hh]);
        float2 e23 = upk2(s2[2 * hh + 1]);
        *(float4*)&sm[warp * 512 + hh * 128 + lane * 4] =
            make_float4(e01.x, e01.y, e23.x, e23.y);
    }
    if ((lane & 7) == 0) sl[warp][lane >> 3] = l_acc;
    __syncthreads();

    const size_t base = (size_t)bp * 8 * E_;
    #pragma unroll
    for (int k = 0; k < 4; k++) {
        int idx = tid + k * 256;
        int hh = idx >> 7, e = idx & 127;
        int w0 = (hh >> 2) * 4, hi = hh & 3;
        float a = 0.0f;
        #pragma unroll
        for (int w = 0; w < 4; w++) a += sm[(w0 + w) * 512 + hi * 128 + e];
        g_ps[base + idx] = a;
    }
    if (tid < 8) {
        int w0 = (tid >> 2) * 4, hi = tid & 3;
        float a = 0.0f;
        #pragma unroll
        for (int w = 0; w < 4; w++) a += sl[w0 + w][hi];
        g_pl[bp * 8 + tid] = a;
    }
}

// ---------------------------------------------------------------------------
// K2: 8 batches per block — weights load-once-use-8, 8-way ILP chains.
// ---------------------------------------------------------------------------
__global__ void __launch_bounds__(128) k_epilogue(
    const float* __restrict__ Vb,  const float* __restrict__ Wob,
    const float* __restrict__ Qfb,
    const float* __restrict__ Kfw, const float* __restrict__ Kfb)
{
    const int b0 = blockIdx.x * EB, tid = threadIdx.x;
    const int warp = tid >> 5, lane = tid & 31;

    __shared__ float sbar[EB][8 * 132];    // 33.8 KB, pad-132
    __shared__ float ctx[EB][128], dec[EB][128], qf[EB][128];
    __shared__ float invl[EB][8];

    if (tid < 64) {
        int bb = tid >> 3, hh = tid & 7;
        float L = 0.0f;
        #pragma unroll
        for (int p = 0; p < SPLIT; p++)
            L += g_pl[((b0 + bb) * SPLIT + p) * 8 + hh];
        invl[bb][hh] = 1.0f / L;
    }
    __syncthreads();

    #pragma unroll 1
    for (int bb = 0; bb < EB; bb++)
        #pragma unroll
        for (int hh = 0; hh < 8; hh++) {
            float a = 0.0f;
            #pragma unroll
            for (int p = 0; p < SPLIT; p++)
                a += g_ps[(size_t)((b0 + bb) * SPLIT + p) * 8 * E_ + hh * E_ + tid];
            sbar[bb][hh * 132 + tid] = a * invl[bb][hh];
        }
    __syncthreads();

    {   // ctx
        const int hb_ = (tid >> 4) * 132;
        float vb0 = Vb[tid];
        float a[EB];
        #pragma unroll
        for (int bb = 0; bb < EB; bb++) a[bb] = vb0;
        #pragma unroll 4
        for (int k = 0; k < 128; k++) {
            float w = g_VwT[k * 128 + tid];
            #pragma unroll
            for (int bb = 0; bb < EB; bb++) a[bb] += w * sbar[bb][hb_ + k];
        }
        #pragma unroll
        for (int bb = 0; bb < EB; bb++) ctx[bb][tid] = a[bb];
    }
    __syncthreads();
    {   // dec
        float wb0 = Wob[tid];
        float a[EB];
        #pragma unroll
        for (int bb = 0; bb < EB; bb++) a[bb] = wb0;
        #pragma unroll 4
        for (int k = 0; k < 128; k++) {
            float w = g_WowT[k * 128 + tid];
            #pragma unroll
            for (int bb = 0; bb < EB; bb++) a[bb] += w * ctx[bb][k];
        }
        #pragma unroll
        for (int bb = 0; bb < EB; bb++) dec[bb][tid] = a[bb];
    }
    __syncthreads();
    {   // qf
        float qb0 = Qfb[tid];
        float a[EB];
        #pragma unroll
        for (int bb = 0; bb < EB; bb++) a[bb] = qb0;
        #pragma unroll 4
        for (int k = 0; k < 128; k++) {
            float w = g_QfwT[k * 128 + tid];
            #pragma unroll
            for (int bb = 0; bb < EB; bb++) a[bb] += w * dec[bb][k];
        }
        #pragma unroll
        for (int bb = 0; bb < EB; bb++) qf[bb][tid] = a[bb];
    }
    __syncthreads();

    {   // w[k] = sum_j qf[j] * Kfw[j][k]
        float a[EB];
        #pragma unroll
        for (int bb = 0; bb < EB; bb++) a[bb] = 0.0f;
        #pragma unroll 4
        for (int j = 0; j < 128; j++) {
            float w = Kfw[(size_t)j * E_ + tid];
            #pragma unroll
            for (int bb = 0; bb < EB; bb++) a[bb] += qf[bb][j] * w;
        }
        #pragma unroll
        for (int bb = 0; bb < EB; bb++)
            g_w[(b0 + bb) * 128 + tid] = a[bb];
    }

    // kb: warp handles 2 batches
    #pragma unroll
    for (int s = 0; s < 2; s++) {
        int bb = warp * 2 + s;
        float a = 0.0f;
        #pragma unroll
        for (int q = 0; q < 4; q++)
            a += qf[bb][lane + 32 * q] * Kfb[lane + 32 * q];
        #pragma unroll
        for (int off = 16; off; off >>= 1)
            a += __shfl_xor_sync(0xffffffffu, a, off);
        if (lane == 0) g_kb[b0 + bb] = a;
    }
}

// ---------------------------------------------------------------------------
// K3: logits. Masked rows: write -1e8, never touch h. Unmasked: paired fold.
// ---------------------------------------------------------------------------
__global__ void __launch_bounds__(256) k_logits(
    const float* __restrict__ h, const int* __restrict__ mask,
    float* __restrict__ out)
{
    const int b = blockIdx.y, chunk = blockIdx.x;
    const int warp = threadIdx.x >> 5, lane = threadIdx.x & 31;

    float4 w4 = *(const float4*)&g_w[b * 128 + lane * 4];
    float  kb = g_kb[b];

    const int c0 = chunk * 256 + warp * 32;
    const float* rbase = h + ((size_t)b * C_ + c0) * E_ + lane * 4;
    float* ob = out + (size_t)b * C_ + c0;

    const int m = mask[b * C_ + c0 + lane];
    unsigned bits = __ballot_sync(0xffffffffu, m == 0);
    if (m) ob[lane] = -1.0e8f;

    const bool hi = (lane & 16) != 0;

    int i0 = -1, i1 = -1;
    if (bits) { i0 = __ffs(bits) - 1; bits &= bits - 1; }
    if (bits) { i1 = __ffs(bits) - 1; bits &= bits - 1; }
    float4 A0 = make_float4(0.f, 0.f, 0.f, 0.f), A1 = A0;
    if (i0 >= 0) {
        A0 = *(const float4*)(rbase + (size_t)i0 * E_);
        A1 = *(const float4*)(rbase + (size_t)(i1 >= 0 ? i1 : i0) * E_);
    }

    while (i0 >= 0) {
        int n0 = -1, n1 = -1;
        if (bits) { n0 = __ffs(bits) - 1; bits &= bits - 1; }
        if (bits) { n1 = __ffs(bits) - 1; bits &= bits - 1; }
        float4 N0, N1;
        if (n0 >= 0) {
            N0 = *(const float4*)(rbase + (size_t)n0 * E_);
            N1 = *(const float4*)(rbase + (size_t)(n1 >= 0 ? n1 : n0) * E_);
        }

        float p0 = A0.x * w4.x + A0.y * w4.y + A0.z * w4.z + A0.w * w4.w;
        float p1 = A1.x * w4.x + A1.y * w4.y + A1.z * w4.z + A1.w * w4.w;

        float send = hi ? p0 : p1;
        float keep = hi ? p1 : p0;
        float t = keep + __shfl_xor_sync(0xffffffffu, send, 16);
        t += __shfl_xor_sync(0xffffffffu, t, 8);
        t += __shfl_xor_sync(0xffffffffu, t, 4);
        t += __shfl_xor_sync(0xffffffffu, t, 2);
        t += __shfl_xor_sync(0xffffffffu, t, 1);

        float lg = (t + kb) * 0.08838834764831845f;
        float val = 10.0f * tanhf(lg);
        if (lane == 0)                  ob[i0] = val;
        else if (lane == 16 && i1 >= 0) ob[i1] = val;

        i0 = n0; i1 = n1; A0 = N0; A1 = N1;
    }
}

// ---------------------------------------------------------------------------
extern "C" void kernel_launch(void* const* d_in, const int* in_sizes, int n_in,
                              void* d_out, int out_size) {
    const float* h    = (const float*)d_in[0];
    const float* hN   = (const float*)d_in[1];
    const float* hpr  = (const float*)d_in[2];
    const float* h0   = (const float*)d_in[3];
    const int*   mask = (const int*)  d_in[4];
    const float* Qw   = (const float*)d_in[5];
    const float* Qb   = (const float*)d_in[6];
    const float* Vw   = (const float*)d_in[7];
    const float* Vb   = (const float*)d_in[8];
    const float* Wow  = (const float*)d_in[9];
    const float* Wob  = (const float*)d_in[10];
    const float* Qfw  = (const float*)d_in[11];
    const float* Qfb  = (const float*)d_in[12];
    const float* Kfw  = (const float*)d_in[13];
    const float* Kfb  = (const float*)d_in[14];
    float* out = (float*)d_out;

    const int DSMEM = 2 * TROWS * E_ * (int)sizeof(float);   // 64 KB
    cudaFuncSetAttribute(k_fused, cudaFuncAttributeMaxDynamicSharedMemorySize, DSMEM);

    k_setup   <<<dim3(SPLIT, B_), 256>>>(mask, Vw, Wow, Qfw, Qw);
    k_prep    <<<B_ / PB, 128>>>(hN, hpr, h0, Qb, Vw, Vb);
    k_fused   <<<dim3(SPLIT, B_), 256, DSMEM>>>(h);
    k_epilogue<<<B_ / EB, 128>>>(Vb, Wob, Qfb, Kfw, Kfb);
    k_logits  <<<dim3(4, B_), 256>>>(h, mask, out);
}